// round 6
// baseline (speedup 1.0000x reference)
#include <cuda_runtime.h>
#include <cstdint>

#define NLEV 16
#define LOG2T 19
#define TSIZE (1u << LOG2T)
#define TMASK (TSIZE - 1u)
#define P1 2654435761u
#define P2 805459861u

#define D0 17
#define D1 33
#define D2 65
#define N_D1 (D1 * D1 * D1)   // 35937
#define N_D2 (D2 * D2 * D2)   // 274625

// Dense mirrors of hashed tables for levels 1 and 2 (level 0 lives in smem).
__device__ float2 g_dense1[N_D1];   // 287 KB
__device__ float2 g_dense2[N_D2];   // 2.2 MB

__global__ __launch_bounds__(256) void build_dense_kernel(const float* __restrict__ tables)
{
    int i = blockIdx.x * blockDim.x + threadIdx.x;
    const float2* t = reinterpret_cast<const float2*>(tables);
    if (i < N_D1) {
        uint32_t iz = i % D1, iy = (i / D1) % D1, ix = i / (D1 * D1);
        uint32_t h = (ix ^ (iy * P1) ^ (iz * P2) ^ 1u) & TMASK;
        g_dense1[i] = t[(size_t)1 * TSIZE + h];
    } else {
        int k = i - N_D1;
        if (k < N_D2) {
            uint32_t iz = k % D2, iy = (k / D2) % D2, ix = k / (D2 * D2);
            uint32_t h = (ix ^ (iy * P1) ^ (iz * P2) ^ 2u) & TMASK;
            g_dense2[k] = t[(size_t)2 * TSIZE + h];
        }
    }
}

// Persistent main kernel: 512 threads = 16 warps, warp w handles level w.
__global__ __launch_bounds__(512, 3) void hashenc_main(
    const float* __restrict__ x,
    const float* __restrict__ tables,
    float* __restrict__ out,
    int N)
{
    __shared__ float2 s_d0[D0 * D0 * D0];   // 4913 * 8B = 39.3 KB
    __shared__ float  s_x[96];              // 32 points * 3
    __shared__ float  s_o[32 * 33];         // padded (stride 33) output stage

    const float2* t = reinterpret_cast<const float2*>(tables);
    int tid = threadIdx.x;

    // Build level-0 dense grid once per block (same addrs chip-wide -> L2 hits).
    for (int i = tid; i < D0 * D0 * D0; i += 512) {
        uint32_t iz = i % D0, iy = (i / D0) % D0, ix = i / (D0 * D0);
        uint32_t h = (ix ^ (iy * P1) ^ (iz * P2)) & TMASK;   // level 0 -> ^0
        s_d0[i] = __ldg(&t[h]);
    }
    __syncthreads();

    int w = tid >> 5;    // level
    int j = tid & 31;    // point within tile
    int ntiles = (N + 31) >> 5;

    for (int tile = blockIdx.x; tile < ntiles; tile += gridDim.x) {
        int n0 = tile << 5;
        int npts = min(32, N - n0);

        if (tid < 3 * npts) s_x[tid] = x[n0 * 3 + tid];
        __syncthreads();

        if (j < npts) {
            float px = s_x[j * 3 + 0];
            float py = s_x[j * 3 + 1];
            float pz = s_x[j * 3 + 2];

            const float HI = 1.0f - 1e-6f;
            float nx = fminf(fmaxf((px + 1.0f) * 0.5f, 0.0f), HI);
            float ny = fminf(fmaxf((py + 1.0f) * 0.5f, 0.0f), HI);
            float nz = fminf(fmaxf((pz + 1.0f) * 0.5f, 0.0f), HI);

            float res = (float)(16 << w);
            float sx = nx * res, sy = ny * res, sz = nz * res;
            float fxf = floorf(sx), fyf = floorf(sy), fzf = floorf(sz);
            float fx = sx - fxf, fy = sy - fyf, fz = sz - fzf;

            uint32_t ix = (uint32_t)(int)fxf;
            uint32_t iy = (uint32_t)(int)fyf;
            uint32_t iz = (uint32_t)(int)fzf;

            float2 e0, e1, e2, e3, e4, e5, e6, e7;
            if (w == 0) {
                int li = ((int)ix * D0 + (int)iy) * D0 + (int)iz;
                e0 = s_d0[li];
                e1 = s_d0[li + 1];
                e2 = s_d0[li + D0];
                e3 = s_d0[li + D0 + 1];
                e4 = s_d0[li + D0 * D0];
                e5 = s_d0[li + D0 * D0 + 1];
                e6 = s_d0[li + D0 * D0 + D0];
                e7 = s_d0[li + D0 * D0 + D0 + 1];
            } else if (w == 1) {
                int li = ((int)ix * D1 + (int)iy) * D1 + (int)iz;
                e0 = __ldg(&g_dense1[li]);
                e1 = __ldg(&g_dense1[li + 1]);
                e2 = __ldg(&g_dense1[li + D1]);
                e3 = __ldg(&g_dense1[li + D1 + 1]);
                e4 = __ldg(&g_dense1[li + D1 * D1]);
                e5 = __ldg(&g_dense1[li + D1 * D1 + 1]);
                e6 = __ldg(&g_dense1[li + D1 * D1 + D1]);
                e7 = __ldg(&g_dense1[li + D1 * D1 + D1 + 1]);
            } else if (w == 2) {
                int li = ((int)ix * D2 + (int)iy) * D2 + (int)iz;
                e0 = __ldg(&g_dense2[li]);
                e1 = __ldg(&g_dense2[li + 1]);
                e2 = __ldg(&g_dense2[li + D2]);
                e3 = __ldg(&g_dense2[li + D2 + 1]);
                e4 = __ldg(&g_dense2[li + D2 * D2]);
                e5 = __ldg(&g_dense2[li + D2 * D2 + 1]);
                e6 = __ldg(&g_dense2[li + D2 * D2 + D2]);
                e7 = __ldg(&g_dense2[li + D2 * D2 + D2 + 1]);
            } else {
                uint32_t hx0 = ix;
                uint32_t hx1 = ix + 1u;
                uint32_t hy0 = iy * P1;
                uint32_t hy1 = (iy + 1u) * P1;
                uint32_t hz0 = iz * P2;
                uint32_t hz1 = (iz + 1u) * P2;
                uint32_t lv = (uint32_t)w;
                const float2* tab = t + (size_t)w * TSIZE;
                uint32_t i0 = (hx0 ^ hy0 ^ hz0 ^ lv) & TMASK;
                uint32_t i1 = (hx0 ^ hy0 ^ hz1 ^ lv) & TMASK;
                uint32_t i2 = (hx0 ^ hy1 ^ hz0 ^ lv) & TMASK;
                uint32_t i3 = (hx0 ^ hy1 ^ hz1 ^ lv) & TMASK;
                uint32_t i4 = (hx1 ^ hy0 ^ hz0 ^ lv) & TMASK;
                uint32_t i5 = (hx1 ^ hy0 ^ hz1 ^ lv) & TMASK;
                uint32_t i6 = (hx1 ^ hy1 ^ hz0 ^ lv) & TMASK;
                uint32_t i7 = (hx1 ^ hy1 ^ hz1 ^ lv) & TMASK;
                e0 = __ldg(&tab[i0]);
                e1 = __ldg(&tab[i1]);
                e2 = __ldg(&tab[i2]);
                e3 = __ldg(&tab[i3]);
                e4 = __ldg(&tab[i4]);
                e5 = __ldg(&tab[i5]);
                e6 = __ldg(&tab[i6]);
                e7 = __ldg(&tab[i7]);
            }

            float wx0 = 1.0f - fx, wx1 = fx;
            float wy0 = 1.0f - fy, wy1 = fy;
            float wz0 = 1.0f - fz, wz1 = fz;

            float w0 = (wx0 * wy0) * wz0;
            float w1 = (wx0 * wy0) * wz1;
            float w2 = (wx0 * wy1) * wz0;
            float w3 = (wx0 * wy1) * wz1;
            float w4 = (wx1 * wy0) * wz0;
            float w5 = (wx1 * wy0) * wz1;
            float w6 = (wx1 * wy1) * wz0;
            float w7 = (wx1 * wy1) * wz1;

            float ox = e0.x * w0 + e1.x * w1 + e2.x * w2 + e3.x * w3
                     + e4.x * w4 + e5.x * w5 + e6.x * w6 + e7.x * w7;
            float oy = e0.y * w0 + e1.y * w1 + e2.y * w2 + e3.y * w3
                     + e4.y * w4 + e5.y * w5 + e6.y * w6 + e7.y * w7;

            s_o[j * 33 + 2 * w + 0] = ox;
            s_o[j * 33 + 2 * w + 1] = oy;
        }
        __syncthreads();

        // Coalesced tile store: 1024 floats (32 points x 32 feats)
        int base = n0 * 32;                 // float offset into out
        int lim = N * 32;
        int g0 = tid, g1 = tid + 512;
        if (base + g0 < lim) out[base + g0] = s_o[(g0 >> 5) * 33 + (g0 & 31)];
        if (base + g1 < lim) out[base + g1] = s_o[(g1 >> 5) * 33 + (g1 & 31)];
        __syncthreads();
    }
}

extern "C" void kernel_launch(void* const* d_in, const int* in_sizes, int n_in,
                              void* d_out, int out_size)
{
    const float* x      = (const float*)d_in[0];   // [N,3]
    const float* tables = (const float*)d_in[1];   // [16, 2^19, 2]
    float* out          = (float*)d_out;           // [N, 32]
    int N = in_sizes[0] / 3;

    int btotal = N_D1 + N_D2;
    build_dense_kernel<<<(btotal + 255) / 256, 256>>>(tables);

    int grid = 152 * 4;   // persistent-style; extra blocks just queue
    hashenc_main<<<grid, 512>>>(x, tables, out, N);
}

// round 7
// speedup vs baseline: 1.4514x; 1.4514x over previous
#include <cuda_runtime.h>
#include <cstdint>

#define NLEV 16
#define LOG2T 19
#define TSIZE (1u << LOG2T)
#define TMASK (TSIZE - 1u)
#define P1 2654435761u
#define P2 805459861u

#define D0 17
#define D1 33
#define D2 65
#define N_D0 (D0 * D0 * D0)            // 4913
#define N_D1 (D1 * D1 * D1)            // 35937
#define N_D2 (D2 * D2 * D2)            // 274625
#define OFF0 0
#define OFF1 N_D0
#define OFF2 (N_D0 + N_D1)
#define N_DENSE (N_D0 + N_D1 + N_D2)   // 315475

// Dense mirrors of the hashed tables for levels 0..2, packed contiguously.
__device__ float2 g_dense[N_DENSE];

__global__ __launch_bounds__(256) void build_dense_kernel(const float* __restrict__ tables)
{
    int i = blockIdx.x * blockDim.x + threadIdx.x;
    if (i >= N_DENSE) return;
    const float2* t = reinterpret_cast<const float2*>(tables);
    int l, k;
    if (i < OFF1)      { l = 0; k = i; }
    else if (i < OFF2) { l = 1; k = i - OFF1; }
    else               { l = 2; k = i - OFF2; }
    int D = (16 << l) + 1;
    uint32_t iz = (uint32_t)(k % D);
    uint32_t iy = (uint32_t)((k / D) % D);
    uint32_t ix = (uint32_t)(k / (D * D));
    uint32_t h = (ix ^ (iy * P1) ^ (iz * P2) ^ (uint32_t)l) & TMASK;
    g_dense[i] = t[(size_t)l * TSIZE + h];
}

__global__ __launch_bounds__(256) void hashenc_kernel(
    const float* __restrict__ x,
    const float* __restrict__ tables,
    float* __restrict__ out,
    int total)   // N * NLEV
{
    int tid = blockIdx.x * blockDim.x + threadIdx.x;
    if (tid >= total) return;
    int n = tid >> 4;
    int l = tid & 15;

    float px = __ldg(&x[n * 3 + 0]);
    float py = __ldg(&x[n * 3 + 1]);
    float pz = __ldg(&x[n * 3 + 2]);

    const float HI = 1.0f - 1e-6f;
    float nx = fminf(fmaxf((px + 1.0f) * 0.5f, 0.0f), HI);
    float ny = fminf(fmaxf((py + 1.0f) * 0.5f, 0.0f), HI);
    float nz = fminf(fmaxf((pz + 1.0f) * 0.5f, 0.0f), HI);

    float res = (float)(16 << l);
    float sx = nx * res, sy = ny * res, sz = nz * res;
    float fxf = floorf(sx), fyf = floorf(sy), fzf = floorf(sz);
    float fx = sx - fxf, fy = sy - fyf, fz = sz - fzf;

    uint32_t ix = (uint32_t)(int)fxf;
    uint32_t iy = (uint32_t)(int)fyf;
    uint32_t iz = (uint32_t)(int)fzf;

    float2 e0, e1, e2, e3, e4, e5, e6, e7;

    if (l < 3) {
        // dense mirror: compact, z-adjacent corners share sectors
        int D = (16 << l) + 1;
        int off = (l == 0) ? OFF0 : (l == 1) ? OFF1 : OFF2;
        const float2* g = g_dense + off;
        int li = ((int)ix * D + (int)iy) * D + (int)iz;
        int DD = D * D;
        e0 = __ldg(&g[li]);
        e1 = __ldg(&g[li + 1]);
        e2 = __ldg(&g[li + D]);
        e3 = __ldg(&g[li + D + 1]);
        e4 = __ldg(&g[li + DD]);
        e5 = __ldg(&g[li + DD + 1]);
        e6 = __ldg(&g[li + DD + D]);
        e7 = __ldg(&g[li + DD + D + 1]);
    } else {
        uint32_t hx0 = ix;
        uint32_t hx1 = ix + 1u;
        uint32_t hy0 = iy * P1;
        uint32_t hy1 = (iy + 1u) * P1;
        uint32_t hz0 = iz * P2;
        uint32_t hz1 = (iz + 1u) * P2;
        uint32_t lv = (uint32_t)l;

        uint32_t i0 = (hx0 ^ hy0 ^ hz0 ^ lv) & TMASK;
        uint32_t i1 = (hx0 ^ hy0 ^ hz1 ^ lv) & TMASK;
        uint32_t i2 = (hx0 ^ hy1 ^ hz0 ^ lv) & TMASK;
        uint32_t i3 = (hx0 ^ hy1 ^ hz1 ^ lv) & TMASK;
        uint32_t i4 = (hx1 ^ hy0 ^ hz0 ^ lv) & TMASK;
        uint32_t i5 = (hx1 ^ hy0 ^ hz1 ^ lv) & TMASK;
        uint32_t i6 = (hx1 ^ hy1 ^ hz0 ^ lv) & TMASK;
        uint32_t i7 = (hx1 ^ hy1 ^ hz1 ^ lv) & TMASK;

        const float2* __restrict__ tab =
            reinterpret_cast<const float2*>(tables) + (size_t)l * TSIZE;

        e0 = __ldg(&tab[i0]);
        e1 = __ldg(&tab[i1]);
        e2 = __ldg(&tab[i2]);
        e3 = __ldg(&tab[i3]);
        e4 = __ldg(&tab[i4]);
        e5 = __ldg(&tab[i5]);
        e6 = __ldg(&tab[i6]);
        e7 = __ldg(&tab[i7]);
    }

    float wx0 = 1.0f - fx, wx1 = fx;
    float wy0 = 1.0f - fy, wy1 = fy;
    float wz0 = 1.0f - fz, wz1 = fz;

    float w0 = (wx0 * wy0) * wz0;
    float w1 = (wx0 * wy0) * wz1;
    float w2 = (wx0 * wy1) * wz0;
    float w3 = (wx0 * wy1) * wz1;
    float w4 = (wx1 * wy0) * wz0;
    float w5 = (wx1 * wy0) * wz1;
    float w6 = (wx1 * wy1) * wz0;
    float w7 = (wx1 * wy1) * wz1;

    float ox0 = e0.x * w0 + e1.x * w1 + e2.x * w2 + e3.x * w3
              + e4.x * w4 + e5.x * w5 + e6.x * w6 + e7.x * w7;
    float oy0 = e0.y * w0 + e1.y * w1 + e2.y * w2 + e3.y * w3
              + e4.y * w4 + e5.y * w5 + e6.y * w6 + e7.y * w7;

    reinterpret_cast<float2*>(out)[(size_t)n * NLEV + l] = make_float2(ox0, oy0);
}

extern "C" void kernel_launch(void* const* d_in, const int* in_sizes, int n_in,
                              void* d_out, int out_size)
{
    const float* x      = (const float*)d_in[0];   // [N,3]
    const float* tables = (const float*)d_in[1];   // [16, 2^19, 2]
    float* out          = (float*)d_out;           // [N, 32]
    int N = in_sizes[0] / 3;

    build_dense_kernel<<<(N_DENSE + 255) / 256, 256>>>(tables);

    int total = N * NLEV;
    int threads = 256;
    int blocks = (total + threads - 1) / threads;
    hashenc_kernel<<<blocks, threads>>>(x, tables, out, total);
}

// round 8
// speedup vs baseline: 1.4634x; 1.0083x over previous
#include <cuda_runtime.h>
#include <cstdint>

#define NLEV 16
#define LOG2T 19
#define TSIZE (1u << LOG2T)
#define TMASK (TSIZE - 1u)
#define P1 2654435761u
#define P2 805459861u

#define D0 17
#define D1 33
#define D2 65
#define N_D0 (D0 * D0 * D0)            // 4913
#define N_D1 (D1 * D1 * D1)            // 35937
#define N_D2 (D2 * D2 * D2)            // 274625
#define OFF0 0
#define OFF1 N_D0
#define OFF2 (N_D0 + N_D1)
#define N_DENSE (N_D0 + N_D1 + N_D2)   // 315475

// Dense mirrors of levels 0..2 as z-PAIRS: d4[li] = { tab[...z], tab[...z+1] }.
// One aligned 16B load fetches both z-corners of a trilinear pair.
__device__ float4 g_dense4[N_DENSE];   // ~5 MB

__global__ __launch_bounds__(256) void build_dense_kernel(const float* __restrict__ tables)
{
    int i = blockIdx.x * blockDim.x + threadIdx.x;
    if (i >= N_DENSE) return;
    const float2* t = reinterpret_cast<const float2*>(tables);
    int l, k;
    if (i < OFF1)      { l = 0; k = i; }
    else if (i < OFF2) { l = 1; k = i - OFF1; }
    else               { l = 2; k = i - OFF2; }
    int D = (16 << l) + 1;
    uint32_t iz = (uint32_t)(k % D);
    uint32_t iy = (uint32_t)((k / D) % D);
    uint32_t ix = (uint32_t)(k / (D * D));
    uint32_t hbase = ix ^ (iy * P1) ^ (uint32_t)l;
    uint32_t h0 = (hbase ^ (iz * P2)) & TMASK;
    uint32_t h1 = (hbase ^ ((iz + 1u) * P2)) & TMASK;   // iz+1==D never read as pair base; harmless
    float2 a = t[(size_t)l * TSIZE + h0];
    float2 b = t[(size_t)l * TSIZE + h1];
    g_dense4[i] = make_float4(a.x, a.y, b.x, b.y);
}

__global__ __launch_bounds__(256) void hashenc_kernel(
    const float* __restrict__ x,
    const float* __restrict__ tables,
    float* __restrict__ out,
    int total)   // N * NLEV
{
    int tid = blockIdx.x * blockDim.x + threadIdx.x;
    if (tid >= total) return;
    int n = tid >> 4;
    int l = tid & 15;

    float px = __ldg(&x[n * 3 + 0]);
    float py = __ldg(&x[n * 3 + 1]);
    float pz = __ldg(&x[n * 3 + 2]);

    const float HI = 1.0f - 1e-6f;
    float nx = fminf(fmaxf((px + 1.0f) * 0.5f, 0.0f), HI);
    float ny = fminf(fmaxf((py + 1.0f) * 0.5f, 0.0f), HI);
    float nz = fminf(fmaxf((pz + 1.0f) * 0.5f, 0.0f), HI);

    float res = (float)(16 << l);
    float sx = nx * res, sy = ny * res, sz = nz * res;
    float fxf = floorf(sx), fyf = floorf(sy), fzf = floorf(sz);
    float fx = sx - fxf, fy = sy - fyf, fz = sz - fzf;

    uint32_t ix = (uint32_t)(int)fxf;
    uint32_t iy = (uint32_t)(int)fyf;
    uint32_t iz = (uint32_t)(int)fzf;

    float2 e0, e1, e2, e3, e4, e5, e6, e7;

    if (l < 3) {
        // dense mirror, z-pairs: 4 aligned LDG.128 instead of 8 LDG.64
        int D = (16 << l) + 1;
        int off = (l == 0) ? OFF0 : (l == 1) ? OFF1 : OFF2;
        const float4* g = g_dense4 + off;
        int li = ((int)ix * D + (int)iy) * D + (int)iz;
        int DD = D * D;
        float4 p01 = __ldg(&g[li]);
        float4 p23 = __ldg(&g[li + D]);
        float4 p45 = __ldg(&g[li + DD]);
        float4 p67 = __ldg(&g[li + DD + D]);
        e0 = make_float2(p01.x, p01.y); e1 = make_float2(p01.z, p01.w);
        e2 = make_float2(p23.x, p23.y); e3 = make_float2(p23.z, p23.w);
        e4 = make_float2(p45.x, p45.y); e5 = make_float2(p45.z, p45.w);
        e6 = make_float2(p67.x, p67.y); e7 = make_float2(p67.z, p67.w);
    } else {
        uint32_t hx0 = ix;
        uint32_t hx1 = ix + 1u;
        uint32_t hy0 = iy * P1;
        uint32_t hy1 = (iy + 1u) * P1;
        uint32_t hz0 = iz * P2;
        uint32_t hz1 = (iz + 1u) * P2;
        uint32_t lv = (uint32_t)l;

        uint32_t i0 = (hx0 ^ hy0 ^ hz0 ^ lv) & TMASK;
        uint32_t i1 = (hx0 ^ hy0 ^ hz1 ^ lv) & TMASK;
        uint32_t i2 = (hx0 ^ hy1 ^ hz0 ^ lv) & TMASK;
        uint32_t i3 = (hx0 ^ hy1 ^ hz1 ^ lv) & TMASK;
        uint32_t i4 = (hx1 ^ hy0 ^ hz0 ^ lv) & TMASK;
        uint32_t i5 = (hx1 ^ hy0 ^ hz1 ^ lv) & TMASK;
        uint32_t i6 = (hx1 ^ hy1 ^ hz0 ^ lv) & TMASK;
        uint32_t i7 = (hx1 ^ hy1 ^ hz1 ^ lv) & TMASK;

        const float2* __restrict__ tab =
            reinterpret_cast<const float2*>(tables) + (size_t)l * TSIZE;

        e0 = __ldg(&tab[i0]);
        e1 = __ldg(&tab[i1]);
        e2 = __ldg(&tab[i2]);
        e3 = __ldg(&tab[i3]);
        e4 = __ldg(&tab[i4]);
        e5 = __ldg(&tab[i5]);
        e6 = __ldg(&tab[i6]);
        e7 = __ldg(&tab[i7]);
    }

    float wx0 = 1.0f - fx, wx1 = fx;
    float wy0 = 1.0f - fy, wy1 = fy;
    float wz0 = 1.0f - fz, wz1 = fz;

    float w0 = (wx0 * wy0) * wz0;
    float w1 = (wx0 * wy0) * wz1;
    float w2 = (wx0 * wy1) * wz0;
    float w3 = (wx0 * wy1) * wz1;
    float w4 = (wx1 * wy0) * wz0;
    float w5 = (wx1 * wy0) * wz1;
    float w6 = (wx1 * wy1) * wz0;
    float w7 = (wx1 * wy1) * wz1;

    float ox0 = e0.x * w0 + e1.x * w1 + e2.x * w2 + e3.x * w3
              + e4.x * w4 + e5.x * w5 + e6.x * w6 + e7.x * w7;
    float oy0 = e0.y * w0 + e1.y * w1 + e2.y * w2 + e3.y * w3
              + e4.y * w4 + e5.y * w5 + e6.y * w6 + e7.y * w7;

    reinterpret_cast<float2*>(out)[(size_t)n * NLEV + l] = make_float2(ox0, oy0);
}

extern "C" void kernel_launch(void* const* d_in, const int* in_sizes, int n_in,
                              void* d_out, int out_size)
{
    const float* x      = (const float*)d_in[0];   // [N,3]
    const float* tables = (const float*)d_in[1];   // [16, 2^19, 2]
    float* out          = (float*)d_out;           // [N, 32]
    int N = in_sizes[0] / 3;

    build_dense_kernel<<<(N_DENSE + 255) / 256, 256>>>(tables);

    int total = N * NLEV;
    int threads = 256;
    int blocks = (total + threads - 1) / threads;
    hashenc_kernel<<<blocks, threads>>>(x, tables, out, total);
}